// round 1
// baseline (speedup 1.0000x reference)
#include <cuda_runtime.h>

// MVGeometricProduct: out[b,n,j] = sum_{i,k} cayley[i,j,k] * w8[n,gi,gj,gk] * v[b,n,i] * wn[b,n,k]
// D=3, NB=8, blades ordered [0,1,2,4,3,5,6,7], grades [0,1,1,1,2,2,2,3], 20 weight paths.
// One thread per (b,n) site. HBM-bound: ~75.6 MB total traffic.

__global__ __launch_bounds__(256) void mv_gp_kernel(
    const float* __restrict__ v,
    const float* __restrict__ w,
    const float* __restrict__ weight,
    const float* __restrict__ a,
    float* __restrict__ out,
    int total, int F)
{
    int t = blockIdx.x * blockDim.x + threadIdx.x;
    if (t >= total) return;
    int n = t % F;

    // ---- loads: v and w, 8 floats each, as 2x float4 (coalesced) ----
    const float4* v4 = (const float4*)(v + (size_t)t * 8);
    const float4* w4 = (const float4*)(w + (size_t)t * 8);
    float4 va = v4[0], vb = v4[1];
    float4 wa = w4[0], wb = w4[1];

    float vi[8] = {va.x, va.y, va.z, va.w, vb.x, vb.y, vb.z, vb.w};
    float ww[8] = {wa.x, wa.y, wa.z, wa.w, wb.x, wb.y, wb.z, wb.w};

    // ---- per-feature weight row (20 paths) and gate 'a' (4 grades) ----
    float wt[20];
    const float* wp = weight + (size_t)n * 20;
#pragma unroll
    for (int p = 0; p < 20; ++p) wt[p] = __ldg(wp + p);

    const float4 a4 = *(const float4*)(a + (size_t)n * 4);

    // ---- grade-wise normalization of w ----
    float n0 = fabsf(ww[0]);
    float n1 = sqrtf(ww[1]*ww[1] + ww[2]*ww[2] + ww[3]*ww[3]);
    float n2 = sqrtf(ww[4]*ww[4] + ww[5]*ww[5] + ww[6]*ww[6]);
    float n3 = fabsf(ww[7]);

    float s0 = 1.0f / (1.0f + expf(-a4.x));
    float s1 = 1.0f / (1.0f + expf(-a4.y));
    float s2 = 1.0f / (1.0f + expf(-a4.z));
    float s3 = 1.0f / (1.0f + expf(-a4.w));

    float r0 = 1.0f / (s0 * (n0 - 1.0f) + 1.0f);
    float r1 = 1.0f / (s1 * (n1 - 1.0f) + 1.0f);
    float r2 = 1.0f / (s2 * (n2 - 1.0f) + 1.0f);
    float r3 = 1.0f / (s3 * (n3 - 1.0f) + 1.0f);

    float wn[8];
    wn[0] = ww[0] * r0;
    wn[1] = ww[1] * r1;  wn[2] = ww[2] * r1;  wn[3] = ww[3] * r1;
    wn[4] = ww[4] * r2;  wn[5] = ww[5] * r2;  wn[6] = ww[6] * r2;
    wn[7] = ww[7] * r3;

    // ---- 64-term sparse bilinear form ----
    float o[8] = {0.f, 0.f, 0.f, 0.f, 0.f, 0.f, 0.f, 0.f};

#define T(I, K, J, S, P) o[J] = fmaf((S) * wt[P] * vi[I], wn[K], o[J]);

    // i = 0 (scalar, grade 0)
    T(0,0,0, 1.f, 0)  T(0,1,1, 1.f, 1)  T(0,2,2, 1.f, 1)  T(0,3,3, 1.f, 1)
    T(0,4,4, 1.f, 2)  T(0,5,5, 1.f, 2)  T(0,6,6, 1.f, 2)  T(0,7,7, 1.f, 3)
    // i = 1 (e1, grade 1)
    T(1,0,1, 1.f, 5)  T(1,1,0, 1.f, 4)  T(1,2,4, 1.f, 7)  T(1,3,5, 1.f, 7)
    T(1,4,2, 1.f, 6)  T(1,5,3, 1.f, 6)  T(1,6,7, 1.f, 9)  T(1,7,6, 1.f, 8)
    // i = 2 (e2, grade 1)
    T(2,0,2, 1.f, 5)  T(2,1,4,-1.f, 7)  T(2,2,0, 1.f, 4)  T(2,3,6, 1.f, 7)
    T(2,4,1,-1.f, 6)  T(2,5,7,-1.f, 9)  T(2,6,3, 1.f, 6)  T(2,7,5,-1.f, 8)
    // i = 3 (e3, grade 1)
    T(3,0,3, 1.f, 5)  T(3,1,5,-1.f, 7)  T(3,2,6,-1.f, 7)  T(3,3,0, 1.f, 4)
    T(3,4,7, 1.f, 9)  T(3,5,1,-1.f, 6)  T(3,6,2,-1.f, 6)  T(3,7,4, 1.f, 8)
    // i = 4 (e12, grade 2)
    T(4,0,4,-1.f,13)  T(4,1,2, 1.f,11)  T(4,2,1,-1.f,11)  T(4,3,7,-1.f,15)
    T(4,4,0, 1.f,10)  T(4,5,6, 1.f,14)  T(4,6,5,-1.f,14)  T(4,7,3, 1.f,12)
    // i = 5 (e13, grade 2)
    T(5,0,5,-1.f,13)  T(5,1,3, 1.f,11)  T(5,2,7, 1.f,15)  T(5,3,1,-1.f,11)
    T(5,4,6,-1.f,14)  T(5,5,0, 1.f,10)  T(5,6,4, 1.f,14)  T(5,7,2,-1.f,12)
    // i = 6 (e23, grade 2)
    T(6,0,6,-1.f,13)  T(6,1,7,-1.f,15)  T(6,2,3, 1.f,11)  T(6,3,2,-1.f,11)
    T(6,4,5, 1.f,14)  T(6,5,4,-1.f,14)  T(6,6,0, 1.f,10)  T(6,7,1, 1.f,12)
    // i = 7 (e123, grade 3)
    T(7,0,7,-1.f,19)  T(7,1,6,-1.f,18)  T(7,2,5, 1.f,18)  T(7,3,4,-1.f,18)
    T(7,4,3, 1.f,17)  T(7,5,2,-1.f,17)  T(7,6,1, 1.f,17)  T(7,7,0, 1.f,16)

#undef T

    // ---- store: 2x float4 ----
    float4* o4 = (float4*)(out + (size_t)t * 8);
    o4[0] = make_float4(o[0], o[1], o[2], o[3]);
    o4[1] = make_float4(o[4], o[5], o[6], o[7]);
}

extern "C" void kernel_launch(void* const* d_in, const int* in_sizes, int n_in,
                              void* d_out, int out_size) {
    const float* v      = (const float*)d_in[0];
    const float* w      = (const float*)d_in[1];
    const float* weight = (const float*)d_in[2];
    const float* a      = (const float*)d_in[3];
    float* out = (float*)d_out;

    int total = in_sizes[0] / 8;   // B * F sites
    int F     = in_sizes[3] / 4;   // a is [F, 4]

    int threads = 256;
    int blocks = (total + threads - 1) / threads;
    mv_gp_kernel<<<blocks, threads>>>(v, w, weight, a, out, total, F);
}

// round 2
// speedup vs baseline: 1.2240x; 1.2240x over previous
#include <cuda_runtime.h>

// MVGeometricProduct — HBM-bound (~75.6 MB floor).
// Block = 256 threads covering 256 consecutive features n, U=4 batch rows b.
// weight/a staged via smem (coalesced); sigmoid computed once per feature.

#define NR 256
#define UB 4

__global__ __launch_bounds__(256) void mv_gp_kernel(
    const float* __restrict__ v,
    const float* __restrict__ w,
    const float* __restrict__ weight,
    const float* __restrict__ a,
    float* __restrict__ out,
    int B, int F)
{
    __shared__ float wt_s[20][NR];   // transposed: [path][feature]
    __shared__ float sg_s[4][NR];    // sigmoid(a) per grade

    const int tid = threadIdx.x;
    const int n0  = blockIdx.x * NR;
    const int b0  = blockIdx.y * UB;

    // ---- stage weight rows (coalesced float4, scatter to transposed smem) ----
    {
        const float4* wsrc = (const float4*)(weight + (size_t)n0 * 20);
        const int nv4 = (NR * 20) / 4;   // 1280
        for (int i = tid; i < nv4; i += 256) {
            float4 x = wsrc[i];
            int e = i * 4;
            wt_s[(e + 0) % 20][(e + 0) / 20] = x.x;
            wt_s[(e + 1) % 20][(e + 1) / 20] = x.y;
            wt_s[(e + 2) % 20][(e + 2) / 20] = x.z;
            wt_s[(e + 3) % 20][(e + 3) / 20] = x.w;
        }
        // sigmoid(a[n]) once per feature
        const float4 a4 = *(const float4*)(a + (size_t)(n0 + tid) * 4);
        sg_s[0][tid] = __fdividef(1.0f, 1.0f + __expf(-a4.x));
        sg_s[1][tid] = __fdividef(1.0f, 1.0f + __expf(-a4.y));
        sg_s[2][tid] = __fdividef(1.0f, 1.0f + __expf(-a4.z));
        sg_s[3][tid] = __fdividef(1.0f, 1.0f + __expf(-a4.w));
    }
    __syncthreads();

    // ---- per-thread constants (reused across UB sites) ----
    float wt[20];
#pragma unroll
    for (int p = 0; p < 20; ++p) wt[p] = wt_s[p][tid];
    const float s0 = sg_s[0][tid], s1 = sg_s[1][tid],
                s2 = sg_s[2][tid], s3 = sg_s[3][tid];

    const int n = n0 + tid;

#pragma unroll
    for (int u = 0; u < UB; ++u) {
        const int b = b0 + u;
        if (b >= B) break;
        const size_t site = (size_t)b * F + n;

        const float4* v4 = (const float4*)(v + site * 8);
        const float4* w4 = (const float4*)(w + site * 8);
        float4 va = v4[0], vb = v4[1];
        float4 wa = w4[0], wb = w4[1];

        float vi[8] = {va.x, va.y, va.z, va.w, vb.x, vb.y, vb.z, vb.w};
        float ww[8] = {wa.x, wa.y, wa.z, wa.w, wb.x, wb.y, wb.z, wb.w};

        // grade-wise normalization of w
        float nrm0 = fabsf(ww[0]);
        float nrm1 = __fsqrt_rn(ww[1]*ww[1] + ww[2]*ww[2] + ww[3]*ww[3]);
        float nrm2 = __fsqrt_rn(ww[4]*ww[4] + ww[5]*ww[5] + ww[6]*ww[6]);
        float nrm3 = fabsf(ww[7]);

        float r0 = __fdividef(1.0f, fmaf(s0, nrm0 - 1.0f, 1.0f));
        float r1 = __fdividef(1.0f, fmaf(s1, nrm1 - 1.0f, 1.0f));
        float r2 = __fdividef(1.0f, fmaf(s2, nrm2 - 1.0f, 1.0f));
        float r3 = __fdividef(1.0f, fmaf(s3, nrm3 - 1.0f, 1.0f));

        float wn[8];
        wn[0] = ww[0] * r0;
        wn[1] = ww[1] * r1;  wn[2] = ww[2] * r1;  wn[3] = ww[3] * r1;
        wn[4] = ww[4] * r2;  wn[5] = ww[5] * r2;  wn[6] = ww[6] * r2;
        wn[7] = ww[7] * r3;

        float o[8] = {0.f, 0.f, 0.f, 0.f, 0.f, 0.f, 0.f, 0.f};

#define T(I, K, J, S, P) o[J] = fmaf((S) * wt[P] * vi[I], wn[K], o[J]);
        // i = 0 (scalar)
        T(0,0,0, 1.f, 0)  T(0,1,1, 1.f, 1)  T(0,2,2, 1.f, 1)  T(0,3,3, 1.f, 1)
        T(0,4,4, 1.f, 2)  T(0,5,5, 1.f, 2)  T(0,6,6, 1.f, 2)  T(0,7,7, 1.f, 3)
        // i = 1 (e1)
        T(1,0,1, 1.f, 5)  T(1,1,0, 1.f, 4)  T(1,2,4, 1.f, 7)  T(1,3,5, 1.f, 7)
        T(1,4,2, 1.f, 6)  T(1,5,3, 1.f, 6)  T(1,6,7, 1.f, 9)  T(1,7,6, 1.f, 8)
        // i = 2 (e2)
        T(2,0,2, 1.f, 5)  T(2,1,4,-1.f, 7)  T(2,2,0, 1.f, 4)  T(2,3,6, 1.f, 7)
        T(2,4,1,-1.f, 6)  T(2,5,7,-1.f, 9)  T(2,6,3, 1.f, 6)  T(2,7,5,-1.f, 8)
        // i = 3 (e3)
        T(3,0,3, 1.f, 5)  T(3,1,5,-1.f, 7)  T(3,2,6,-1.f, 7)  T(3,3,0, 1.f, 4)
        T(3,4,7, 1.f, 9)  T(3,5,1,-1.f, 6)  T(3,6,2,-1.f, 6)  T(3,7,4, 1.f, 8)
        // i = 4 (e12)
        T(4,0,4,-1.f,13)  T(4,1,2, 1.f,11)  T(4,2,1,-1.f,11)  T(4,3,7,-1.f,15)
        T(4,4,0, 1.f,10)  T(4,5,6, 1.f,14)  T(4,6,5,-1.f,14)  T(4,7,3, 1.f,12)
        // i = 5 (e13)
        T(5,0,5,-1.f,13)  T(5,1,3, 1.f,11)  T(5,2,7, 1.f,15)  T(5,3,1,-1.f,11)
        T(5,4,6,-1.f,14)  T(5,5,0, 1.f,10)  T(5,6,4, 1.f,14)  T(5,7,2,-1.f,12)
        // i = 6 (e23)
        T(6,0,6,-1.f,13)  T(6,1,7,-1.f,15)  T(6,2,3, 1.f,11)  T(6,3,2,-1.f,11)
        T(6,4,5, 1.f,14)  T(6,5,4,-1.f,14)  T(6,6,0, 1.f,10)  T(6,7,1, 1.f,12)
        // i = 7 (e123)
        T(7,0,7,-1.f,19)  T(7,1,6,-1.f,18)  T(7,2,5, 1.f,18)  T(7,3,4,-1.f,18)
        T(7,4,3, 1.f,17)  T(7,5,2,-1.f,17)  T(7,6,1, 1.f,17)  T(7,7,0, 1.f,16)
#undef T

        float4* o4 = (float4*)(out + site * 8);
        o4[0] = make_float4(o[0], o[1], o[2], o[3]);
        o4[1] = make_float4(o[4], o[5], o[6], o[7]);
    }
}

extern "C" void kernel_launch(void* const* d_in, const int* in_sizes, int n_in,
                              void* d_out, int out_size) {
    const float* v      = (const float*)d_in[0];
    const float* w      = (const float*)d_in[1];
    const float* weight = (const float*)d_in[2];
    const float* a      = (const float*)d_in[3];
    float* out = (float*)d_out;

    int F     = in_sizes[3] / 4;        // a is [F, 4]
    int total = in_sizes[0] / 8;        // B * F
    int B     = total / F;

    dim3 grid(F / NR, (B + UB - 1) / UB);
    mv_gp_kernel<<<grid, NR>>>(v, w, weight, a, out, B, F);
}